// round 5
// baseline (speedup 1.0000x reference)
#include <cuda_runtime.h>
#include <cstdint>
#include <cstddef>

#define F_IN  128
#define F_HID 64
#define F_OUT 40
#define MAXN  100032
#define MAXE  1600000
#define SCAN_B 512
#define MAXNB  256   // max scan blocks (N <= 131072)

// ---------------- scratch (no allocation allowed) ----------------
__device__ __align__(256) float g_h1[(size_t)MAXN * F_HID];   // x @ W1^T
__device__ __align__(256) float g_agg1[(size_t)MAXN * F_HID]; // gcn_conv(h1)
__device__ __align__(256) float g_h3[(size_t)MAXN * F_OUT];   // relu(agg1+b1) @ W2^T
__device__ float g_dis[MAXN];
__device__ int   g_cnt[MAXN];
__device__ int   g_rowptr[MAXN + 1];
__device__ int   g_cursor[MAXN];
__device__ int   g_blocksum[MAXNB];
__device__ int   g_perm[MAXE];
__device__ int   g_idx64;     // 1 if edge_index really is int64, 0 if int32

// ---------------- edge dtype detection ----------------
// JAX with default x64-disabled silently emits int32 even when the reference
// asks for int64. Interpreting int32 pairs as int64 yields values >= N almost
// always (high word = second index). Detect on device; deterministic.
__global__ void k_detect(const void* __restrict__ ei, int N) {
    const long long* p64 = (const long long*)ei;
    int bad = 0;
#pragma unroll
    for (int i = 0; i < 64; i++) {
        unsigned long long v = (unsigned long long)p64[i];
        if (v >= (unsigned long long)N) bad++;
    }
    g_idx64 = (bad == 0) ? 1 : 0;
}

__device__ __forceinline__ int edge_at(const void* ei, size_t i, int is64) {
    if (is64) return (int)((const long long*)ei)[i];
    return ((const int*)ei)[i];
}

// ---------------- CSR build ----------------
__global__ void k_zero(int N) {
    int i = blockIdx.x * blockDim.x + threadIdx.x;
    if (i < N) g_cnt[i] = 0;
}

__global__ void k_count(const void* __restrict__ ei, int E, int N) {
    int e = blockIdx.x * blockDim.x + threadIdx.x;
    int is64 = g_idx64;
    if (e < E) {
        int c = edge_at(ei, (size_t)E + e, is64);
        if ((unsigned)c < (unsigned)N) atomicAdd(&g_cnt[c], 1);
    }
}

__global__ void k_dis(int N) {
    int i = blockIdx.x * blockDim.x + threadIdx.x;
    if (i < N) {
        float d = (float)g_cnt[i];
        g_dis[i] = (d > 0.f) ? rsqrtf(d) : 0.f;
    }
}

// block-level inclusive scan -> exclusive offsets (partial) + block sums
__global__ __launch_bounds__(SCAN_B) void k_scan1(int N) {
    __shared__ int s[SCAN_B];
    int t = threadIdx.x;
    int i = blockIdx.x * SCAN_B + t;
    int val = (i < N) ? g_cnt[i] : 0;
    s[t] = val;
    __syncthreads();
#pragma unroll
    for (int off = 1; off < SCAN_B; off <<= 1) {
        int x = (t >= off) ? s[t - off] : 0;
        __syncthreads();
        s[t] += x;
        __syncthreads();
    }
    if (i < N) g_rowptr[i] = s[t] - val;          // exclusive within block
    if (t == SCAN_B - 1) g_blocksum[blockIdx.x] = s[t];
}

// single-block scan of block sums (exclusive), writes rowptr[N] = total
__global__ __launch_bounds__(MAXNB) void k_scan2(int nb, int N) {
    __shared__ int s[MAXNB];
    int t = threadIdx.x;
    int val = (t < nb) ? g_blocksum[t] : 0;
    s[t] = val;
    __syncthreads();
#pragma unroll
    for (int off = 1; off < MAXNB; off <<= 1) {
        int x = (t >= off) ? s[t - off] : 0;
        __syncthreads();
        s[t] += x;
        __syncthreads();
    }
    if (t < nb) g_blocksum[t] = s[t] - val;       // exclusive
    if (t == MAXNB - 1) g_rowptr[N] = s[t];
}

__global__ void k_scan3(int N) {
    int i = blockIdx.x * blockDim.x + threadIdx.x;
    if (i < N) {
        int v = g_rowptr[i] + g_blocksum[i / SCAN_B];
        g_rowptr[i] = v;
        g_cursor[i] = v;
    }
}

__global__ void k_fill(const void* __restrict__ ei, int E, int N) {
    int e = blockIdx.x * blockDim.x + threadIdx.x;
    int is64 = g_idx64;
    if (e < E) {
        int r = edge_at(ei, (size_t)e, is64);
        int c = edge_at(ei, (size_t)E + e, is64);
        if ((unsigned)r < (unsigned)N && (unsigned)c < (unsigned)N) {
            int pos = atomicAdd(&g_cursor[c], 1);
            if ((unsigned)pos < (unsigned)MAXE) g_perm[pos] = r;
        }
    }
}

// ---------------- GEMM1: h1[N,64] = x[N,128] @ W1[64,128]^T ----------------
__global__ __launch_bounds__(256) void gemm1_kernel(const float* __restrict__ x,
                                                    const float* __restrict__ W1, int N) {
    __shared__ float ws[F_HID][32];
    __shared__ float xs[128][33];

    int tid = threadIdx.x;
    int r = tid >> 1;
    int jbase = (tid & 1) * 32;
    int row = blockIdx.x * 128 + r;

    float acc[32];
#pragma unroll
    for (int j = 0; j < 32; j++) acc[j] = 0.f;

#pragma unroll 1
    for (int kp = 0; kp < 4; kp++) {
        __syncthreads();
        for (int i = tid; i < F_HID * 32; i += 256) {
            int j = i >> 5, kk = i & 31;
            ws[j][kk] = W1[j * F_IN + kp * 32 + kk];
        }
        for (int i = tid; i < 128 * 32; i += 256) {
            int rr = i >> 5, kk = i & 31;
            int gr = blockIdx.x * 128 + rr;
            xs[rr][kk] = (gr < N) ? x[(size_t)gr * F_IN + kp * 32 + kk] : 0.f;
        }
        __syncthreads();

        float xr[32];
#pragma unroll
        for (int kk = 0; kk < 32; kk++) xr[kk] = xs[r][kk];
#pragma unroll
        for (int j = 0; j < 32; j++) {
            float s = acc[j];
#pragma unroll
            for (int kk = 0; kk < 32; kk++) s = fmaf(xr[kk], ws[jbase + j][kk], s);
            acc[j] = s;
        }
    }

    if (row < N) {
#pragma unroll
        for (int j = 0; j < 32; j += 4) {
            float4 v = make_float4(acc[j], acc[j + 1], acc[j + 2], acc[j + 3]);
            *(float4*)&g_h1[(size_t)row * F_HID + jbase + j] = v;
        }
    }
}

// ---------------- GEMM2 fused: h3[N,40] = relu(agg1+b1) @ W2[40,64]^T ----------------
__global__ __launch_bounds__(256) void gemm2_kernel(const float* __restrict__ W2,
                                                    const float* __restrict__ b1, int N) {
    __shared__ float ws[F_OUT][32];
    __shared__ float xs[128][33];

    int tid = threadIdx.x;
    int r = tid >> 1;
    int jbase = (tid & 1) * 20;
    int row = blockIdx.x * 128 + r;

    float acc[20];
#pragma unroll
    for (int j = 0; j < 20; j++) acc[j] = 0.f;

#pragma unroll 1
    for (int kp = 0; kp < 2; kp++) {
        __syncthreads();
        for (int i = tid; i < F_OUT * 32; i += 256) {
            int j = i >> 5, kk = i & 31;
            ws[j][kk] = W2[j * F_HID + kp * 32 + kk];
        }
        for (int i = tid; i < 128 * 32; i += 256) {
            int rr = i >> 5, kk = i & 31;
            int gr = blockIdx.x * 128 + rr;
            float v = 0.f;
            if (gr < N) v = g_agg1[(size_t)gr * F_HID + kp * 32 + kk] + b1[kp * 32 + kk];
            xs[rr][kk] = fmaxf(v, 0.f);
        }
        __syncthreads();

        float xr[32];
#pragma unroll
        for (int kk = 0; kk < 32; kk++) xr[kk] = xs[r][kk];
#pragma unroll
        for (int j = 0; j < 20; j++) {
            float s = acc[j];
#pragma unroll
            for (int kk = 0; kk < 32; kk++) s = fmaf(xr[kk], ws[jbase + j][kk], s);
            acc[j] = s;
        }
    }

    if (row < N) {
        float* o = &g_h3[(size_t)row * F_OUT + jbase];
#pragma unroll
        for (int j = 0; j < 20; j += 4) {
            float4 v = make_float4(acc[j], acc[j + 1], acc[j + 2], acc[j + 3]);
            *(float4*)&o[j] = v;
        }
    }
}

// ---------------- aggregation layer 1 (gather, no atomics) ----------------
// warp per node; lanes split into 2 groups of 16 (one edge each); 16 float4 chunks.
__global__ __launch_bounds__(256) void agg1_kernel(int N) {
    int wid = threadIdx.x >> 5;
    int lane = threadIdx.x & 31;
    int node = blockIdx.x * 8 + wid;
    if (node >= N) return;

    int start = g_rowptr[node];
    int end   = g_rowptr[node + 1];
    int half = lane >> 4;      // 0 or 1
    int ch   = lane & 15;      // float4 chunk

    const float4* h = (const float4*)g_h1;
    float4 acc = make_float4(0.f, 0.f, 0.f, 0.f);

    for (int k = start + half; k < end; k += 2) {
        int r = g_perm[k];
        float w = g_dis[r];
        float4 v = __ldg(&h[(size_t)r * 16 + ch]);
        acc.x = fmaf(w, v.x, acc.x);
        acc.y = fmaf(w, v.y, acc.y);
        acc.z = fmaf(w, v.z, acc.z);
        acc.w = fmaf(w, v.w, acc.w);
    }
    acc.x += __shfl_down_sync(0xffffffffu, acc.x, 16);
    acc.y += __shfl_down_sync(0xffffffffu, acc.y, 16);
    acc.z += __shfl_down_sync(0xffffffffu, acc.z, 16);
    acc.w += __shfl_down_sync(0xffffffffu, acc.w, 16);

    if (lane < 16) {
        float di = g_dis[node];
        acc.x *= di; acc.y *= di; acc.z *= di; acc.w *= di;
        ((float4*)g_agg1)[(size_t)node * 16 + ch] = acc;
    }
}

// ---------------- aggregation layer 2 + b2 -> out ----------------
// warp per node; 3 groups of 10 lanes (one edge each); 10 float4 chunks; lanes 30,31 idle.
__global__ __launch_bounds__(256) void agg2_kernel(float* __restrict__ out,
                                                   const float* __restrict__ b2, int N) {
    int wid = threadIdx.x >> 5;
    int lane = threadIdx.x & 31;
    int node = blockIdx.x * 8 + wid;
    if (node >= N) return;

    int start = g_rowptr[node];
    int end   = g_rowptr[node + 1];
    int grp = lane / 10;       // 0,1,2 active; 3 idle
    int ch  = lane - grp * 10;

    const float4* h = (const float4*)g_h3;
    float4 acc = make_float4(0.f, 0.f, 0.f, 0.f);

    if (grp < 3) {
        for (int k = start + grp; k < end; k += 3) {
            int r = g_perm[k];
            float w = g_dis[r];
            float4 v = __ldg(&h[(size_t)r * 10 + ch]);
            acc.x = fmaf(w, v.x, acc.x);
            acc.y = fmaf(w, v.y, acc.y);
            acc.z = fmaf(w, v.z, acc.z);
            acc.w = fmaf(w, v.w, acc.w);
        }
    }
    acc.x += __shfl_down_sync(0xffffffffu, acc.x, 10) + __shfl_down_sync(0xffffffffu, acc.x, 20);
    acc.y += __shfl_down_sync(0xffffffffu, acc.y, 10) + __shfl_down_sync(0xffffffffu, acc.y, 20);
    acc.z += __shfl_down_sync(0xffffffffu, acc.z, 10) + __shfl_down_sync(0xffffffffu, acc.z, 20);
    acc.w += __shfl_down_sync(0xffffffffu, acc.w, 10) + __shfl_down_sync(0xffffffffu, acc.w, 20);

    if (lane < 10) {
        float di = g_dis[node];
        float4 bb = __ldg(&((const float4*)b2)[ch]);
        acc.x = fmaf(acc.x, di, bb.x);
        acc.y = fmaf(acc.y, di, bb.y);
        acc.z = fmaf(acc.z, di, bb.z);
        acc.w = fmaf(acc.w, di, bb.w);
        ((float4*)out)[(size_t)node * 10 + ch] = acc;
    }
}

// ---------------- launch ----------------
extern "C" void kernel_launch(void* const* d_in, const int* in_sizes, int n_in,
                              void* d_out, int out_size) {
    // Bind inputs by UNIQUE element counts (robust to metadata ordering):
    //   x: N*128 = 12,800,000   edge_index: 2*E = 3,200,000
    //   W1: 64*128 = 8192       b1: 64
    //   W2: 40*64  = 2560       b2: 40
    const float* x = nullptr; const void* ei = nullptr;
    const float* W1 = nullptr; const float* b1 = nullptr;
    const float* W2 = nullptr; const float* b2 = nullptr;
    int x_sz = 0, ei_sz = 0;

    for (int i = 0; i < n_in; i++) {
        int s = in_sizes[i];
        if (s == 8192)       W1 = (const float*)d_in[i];
        else if (s == 2560)  W2 = (const float*)d_in[i];
        else if (s == 64)    b1 = (const float*)d_in[i];
        else if (s == 40)    b2 = (const float*)d_in[i];
        else if (s == 12800000) { x = (const float*)d_in[i]; x_sz = s; }
        else if (s == 3200000)  { ei = d_in[i]; ei_sz = s; }
    }
    // positional fallback (reference dict order) if any unmatched
    if (!x || !ei || !W1 || !b1 || !W2 || !b2) {
        x  = (const float*)d_in[0];  x_sz  = in_sizes[0];
        ei = d_in[1];                ei_sz = in_sizes[1];
        W1 = (const float*)d_in[2];
        b1 = (const float*)d_in[3];
        W2 = (const float*)d_in[4];
        b2 = (const float*)d_in[5];
    }

    float* out = (float*)d_out;
    int N = x_sz / F_IN;
    int E = ei_sz / 2;
    if (N > MAXN) N = MAXN;
    if (E > MAXE) E = MAXE;
    int nb = (N + SCAN_B - 1) / SCAN_B;

    // CSR build (int atomics only)
    k_detect<<<1, 1>>>(ei, N);
    k_zero <<<(N + 255) / 256, 256>>>(N);
    k_count<<<(E + 255) / 256, 256>>>(ei, E, N);
    k_dis  <<<(N + 255) / 256, 256>>>(N);
    k_scan1<<<nb, SCAN_B>>>(N);
    k_scan2<<<1, MAXNB>>>(nb, N);
    k_scan3<<<(N + 255) / 256, 256>>>(N);
    k_fill <<<(E + 255) / 256, 256>>>(ei, E, N);

    // dense pipeline
    gemm1_kernel<<<(N + 127) / 128, 256>>>(x, W1, N);
    agg1_kernel <<<(N + 7) / 8, 256>>>(N);
    gemm2_kernel<<<(N + 127) / 128, 256>>>(W2, b1, N);
    agg2_kernel <<<(N + 7) / 8, 256>>>(out, b2, N);
}

// round 6
// speedup vs baseline: 1.3247x; 1.3247x over previous
#include <cuda_runtime.h>
#include <cstdint>
#include <cstddef>

#define F_IN  128
#define F_HID 64
#define F_OUT 40
#define MAXN  100032
#define MAXE  1600000
#define SCAN_B 512
#define MAXNB  256   // max scan blocks (N <= 131072)

// ---------------- scratch (no allocation allowed) ----------------
__device__ __align__(256) float g_h1[(size_t)MAXN * F_HID];   // dis[r] * (x @ W1^T)[r]
__device__ __align__(256) float g_agg1[(size_t)MAXN * F_HID]; // gcn_conv layer-1 result
__device__ __align__(256) float g_h3[(size_t)MAXN * F_OUT];   // dis[r] * (relu(agg1+b1) @ W2^T)[r]
__device__ float g_dis[MAXN];
__device__ int   g_cnt[MAXN];
__device__ int   g_rowptr[MAXN + 1];
__device__ int   g_cursor[MAXN];
__device__ int   g_blocksum[MAXNB];
__device__ int   g_perm[MAXE];
__device__ int   g_idx64;     // 1 if edge_index really is int64, 0 if int32

// ---------------- packed f32x2 helpers ----------------
__device__ __forceinline__ void ffma2(unsigned long long& d, unsigned long long a,
                                      unsigned long long b) {
    asm("fma.rn.f32x2 %0, %1, %2, %0;" : "+l"(d) : "l"(a), "l"(b));
}
__device__ __forceinline__ void unpack2(unsigned long long v, float& x, float& y) {
    asm("mov.b64 {%0, %1}, %2;" : "=f"(x), "=f"(y) : "l"(v));
}

__device__ __forceinline__ int edge_at(const void* ei, size_t i, int is64) {
    if (is64) return (int)((const long long*)ei)[i];
    return ((const int*)ei)[i];
}

// ---------------- K1: zero cnt + dtype detect ----------------
// JAX with x64 disabled silently emits int32 even though reference asks int64.
__global__ void k_zero_detect(const void* __restrict__ ei, int N) {
    int i = blockIdx.x * blockDim.x + threadIdx.x;
    if (i < N) g_cnt[i] = 0;
    if (i == 0) {
        const long long* p64 = (const long long*)ei;
        int bad = 0;
#pragma unroll
        for (int k = 0; k < 64; k++) {
            unsigned long long v = (unsigned long long)p64[k];
            if (v >= (unsigned long long)N) bad++;
        }
        g_idx64 = (bad == 0) ? 1 : 0;
    }
}

// ---------------- K2: in-degree count ----------------
__global__ void k_count(const void* __restrict__ ei, int E, int N) {
    int e = blockIdx.x * blockDim.x + threadIdx.x;
    int is64 = g_idx64;
    if (e < E) {
        int c = edge_at(ei, (size_t)E + e, is64);
        if ((unsigned)c < (unsigned)N) atomicAdd(&g_cnt[c], 1);
    }
}

// ---------------- K3: block scan of cnt (+dis) ----------------
__global__ __launch_bounds__(SCAN_B) void k_scan1(int N) {
    __shared__ int s[SCAN_B];
    int t = threadIdx.x;
    int i = blockIdx.x * SCAN_B + t;
    int val = (i < N) ? g_cnt[i] : 0;
    s[t] = val;
    __syncthreads();
#pragma unroll
    for (int off = 1; off < SCAN_B; off <<= 1) {
        int x = (t >= off) ? s[t - off] : 0;
        __syncthreads();
        s[t] += x;
        __syncthreads();
    }
    if (i < N) {
        g_rowptr[i] = s[t] - val;          // exclusive within block
        float d = (float)val;
        g_dis[i] = (d > 0.f) ? rsqrtf(d) : 0.f;
    }
    if (t == SCAN_B - 1) g_blocksum[blockIdx.x] = s[t];
}

// ---------------- K4: finish scan (each block redundantly scans blocksums) ----
__global__ __launch_bounds__(256) void k_scan23(int N, int nb) {
    __shared__ int s[MAXNB];
    __shared__ int sx[MAXNB + 1];   // exclusive sums; sx[MAXNB] = total
    int t = threadIdx.x;
    int val = (t < nb) ? g_blocksum[t] : 0;
    s[t] = val;
    __syncthreads();
#pragma unroll
    for (int off = 1; off < MAXNB; off <<= 1) {
        int x = (t >= off) ? s[t - off] : 0;
        __syncthreads();
        s[t] += x;
        __syncthreads();
    }
    sx[t] = s[t] - val;
    if (t == MAXNB - 1) sx[MAXNB] = s[t];
    __syncthreads();

    int i = blockIdx.x * 256 + t;
    if (i < N) {
        int v = g_rowptr[i] + sx[i / SCAN_B];
        g_rowptr[i] = v;
        g_cursor[i] = v;
    }
    if (blockIdx.x == 0 && t == 0) g_rowptr[N] = sx[MAXNB];
}

// ---------------- K5: CSR fill ----------------
__global__ void k_fill(const void* __restrict__ ei, int E, int N) {
    int e = blockIdx.x * blockDim.x + threadIdx.x;
    int is64 = g_idx64;
    if (e < E) {
        int r = edge_at(ei, (size_t)e, is64);
        int c = edge_at(ei, (size_t)E + e, is64);
        if ((unsigned)r < (unsigned)N && (unsigned)c < (unsigned)N) {
            int pos = atomicAdd(&g_cursor[c], 1);
            if ((unsigned)pos < (unsigned)MAXE) g_perm[pos] = r;
        }
    }
}

// ---------------- K6: GEMM1  h1' = dis .* (x @ W1^T) ----------------
// 256 thr, 128 rows x 64 cols per block. Thread: 8 rows (4 row-pairs) x 4 cols.
// Packed f32x2: row-pairs packed in xs2, W duplicated in wd -> FFMA2 core.
__global__ __launch_bounds__(256) void gemm1_kernel(const float* __restrict__ x,
                                                    const float* __restrict__ W1, int N) {
    __shared__ float2 xs2[32][65];   // [kk][rowpair] (rows 2rp, 2rp+1)
    __shared__ float2 wd[32][65];    // [kk][j] = (W1[j][k], W1[j][k]) duplicated

    int tid = threadIdx.x;
    int tx = tid & 15;               // col group: cols 4*tx .. 4*tx+3
    int ty = tid >> 4;               // row group: rowpairs 4*ty .. 4*ty+3
    int rbase = blockIdx.x * 128;

    unsigned long long acc[4][4];
#pragma unroll
    for (int r = 0; r < 4; r++)
#pragma unroll
        for (int c = 0; c < 4; c++) acc[r][c] = 0ull;

#pragma unroll 1
    for (int kp = 0; kp < 4; kp++) {
        __syncthreads();
        // stage x: 128 rows x 32 kk
#pragma unroll
        for (int it = 0; it < 16; it++) {
            int idx = it * 256 + tid;
            int rr = idx >> 5, kk = idx & 31;
            int gr = rbase + rr;
            float v = (gr < N) ? x[(size_t)gr * F_IN + kp * 32 + kk] : 0.f;
            ((float*)&xs2[kk][rr >> 1])[rr & 1] = v;
        }
        // stage W duplicated: 64 j x 32 kk
#pragma unroll
        for (int it = 0; it < 8; it++) {
            int idx = it * 256 + tid;
            int j = idx >> 5, kk = idx & 31;
            float v = W1[j * F_IN + kp * 32 + kk];
            wd[kk][j] = make_float2(v, v);
        }
        __syncthreads();

#pragma unroll
        for (int kk = 0; kk < 32; kk++) {
            unsigned long long xp[4], wv[4];
#pragma unroll
            for (int r = 0; r < 4; r++)
                xp[r] = *(const unsigned long long*)&xs2[kk][4 * ty + r];
#pragma unroll
            for (int c = 0; c < 4; c++)
                wv[c] = *(const unsigned long long*)&wd[kk][4 * tx + c];
#pragma unroll
            for (int r = 0; r < 4; r++)
#pragma unroll
                for (int c = 0; c < 4; c++) ffma2(acc[r][c], xp[r], wv[c]);
        }
    }

    // epilogue: scale by dis[row], store 2 rows per rowpair as float4
#pragma unroll
    for (int r = 0; r < 4; r++) {
        int row0 = rbase + 2 * (4 * ty + r);
        if (row0 >= N) break;
        float d0 = g_dis[row0];
        float d1 = (row0 + 1 < N) ? g_dis[row0 + 1] : 0.f;
        float lo[4], hi[4];
#pragma unroll
        for (int c = 0; c < 4; c++) unpack2(acc[r][c], lo[c], hi[c]);
        *(float4*)&g_h1[(size_t)row0 * F_HID + 4 * tx] =
            make_float4(lo[0] * d0, lo[1] * d0, lo[2] * d0, lo[3] * d0);
        if (row0 + 1 < N)
            *(float4*)&g_h1[(size_t)(row0 + 1) * F_HID + 4 * tx] =
                make_float4(hi[0] * d1, hi[1] * d1, hi[2] * d1, hi[3] * d1);
    }
}

// ---------------- K8: GEMM2  h3' = dis .* (relu(agg1+b1) @ W2^T) ----------------
// 256 thr, 128 rows x 40 cols. Thread: 4 rows (2 row-pairs) x 5 cols.
__global__ __launch_bounds__(256) void gemm2_kernel(const float* __restrict__ W2,
                                                    const float* __restrict__ b1, int N) {
    __shared__ float2 xs2[32][65];   // [kk][rowpair]
    __shared__ float2 wd[32][41];    // [kk][j] duplicated

    int tid = threadIdx.x;
    int tx = tid & 7;                // col group: cols 5*tx .. 5*tx+4
    int ty = tid >> 3;               // row group: rowpairs 2*ty, 2*ty+1
    int rbase = blockIdx.x * 128;

    unsigned long long acc[2][5];
#pragma unroll
    for (int r = 0; r < 2; r++)
#pragma unroll
        for (int c = 0; c < 5; c++) acc[r][c] = 0ull;

#pragma unroll 1
    for (int kp = 0; kp < 2; kp++) {
        __syncthreads();
#pragma unroll
        for (int it = 0; it < 16; it++) {
            int idx = it * 256 + tid;
            int rr = idx >> 5, kk = idx & 31;
            int gr = rbase + rr;
            float v = 0.f;
            if (gr < N)
                v = fmaxf(g_agg1[(size_t)gr * F_HID + kp * 32 + kk] + b1[kp * 32 + kk], 0.f);
            ((float*)&xs2[kk][rr >> 1])[rr & 1] = v;
        }
#pragma unroll
        for (int it = 0; it < 5; it++) {
            int idx = it * 256 + tid;
            int j = idx >> 5, kk = idx & 31;
            float v = W2[j * F_HID + kp * 32 + kk];
            wd[kk][j] = make_float2(v, v);
        }
        __syncthreads();

#pragma unroll
        for (int kk = 0; kk < 32; kk++) {
            unsigned long long xp[2], wv[5];
#pragma unroll
            for (int r = 0; r < 2; r++)
                xp[r] = *(const unsigned long long*)&xs2[kk][2 * ty + r];
#pragma unroll
            for (int c = 0; c < 5; c++)
                wv[c] = *(const unsigned long long*)&wd[kk][5 * tx + c];
#pragma unroll
            for (int r = 0; r < 2; r++)
#pragma unroll
                for (int c = 0; c < 5; c++) ffma2(acc[r][c], xp[r], wv[c]);
        }
    }

#pragma unroll
    for (int r = 0; r < 2; r++) {
        int row0 = rbase + 2 * (2 * ty + r);
        if (row0 >= N) break;
        float d0 = g_dis[row0];
        float d1 = (row0 + 1 < N) ? g_dis[row0 + 1] : 0.f;
#pragma unroll
        for (int c = 0; c < 5; c++) {
            float lo, hi;
            unpack2(acc[r][c], lo, hi);
            g_h3[(size_t)row0 * F_OUT + 5 * tx + c] = lo * d0;
            if (row0 + 1 < N) g_h3[(size_t)(row0 + 1) * F_OUT + 5 * tx + c] = hi * d1;
        }
    }
}

// ---------------- K7: aggregation layer 1 (gather, no atomics) ----------------
// warp per node; 2 groups of 16 lanes (one edge each); 16 float4 chunks.
// h1 is pre-scaled by dis[src]; multiply by dis[node] at the end.
__global__ __launch_bounds__(256) void agg1_kernel(int N) {
    int wid = threadIdx.x >> 5;
    int lane = threadIdx.x & 31;
    int node = blockIdx.x * 8 + wid;
    if (node >= N) return;

    int start = g_rowptr[node];
    int end   = g_rowptr[node + 1];
    int half = lane >> 4;
    int ch   = lane & 15;

    const float4* h = (const float4*)g_h1;
    float4 acc = make_float4(0.f, 0.f, 0.f, 0.f);

    for (int k = start + half; k < end; k += 2) {
        int r = g_perm[k];
        float4 v = __ldg(&h[(size_t)r * 16 + ch]);
        acc.x += v.x; acc.y += v.y; acc.z += v.z; acc.w += v.w;
    }
    acc.x += __shfl_down_sync(0xffffffffu, acc.x, 16);
    acc.y += __shfl_down_sync(0xffffffffu, acc.y, 16);
    acc.z += __shfl_down_sync(0xffffffffu, acc.z, 16);
    acc.w += __shfl_down_sync(0xffffffffu, acc.w, 16);

    if (lane < 16) {
        float di = g_dis[node];
        acc.x *= di; acc.y *= di; acc.z *= di; acc.w *= di;
        ((float4*)g_agg1)[(size_t)node * 16 + ch] = acc;
    }
}

// ---------------- K9: aggregation layer 2 + b2 -> out ----------------
__global__ __launch_bounds__(256) void agg2_kernel(float* __restrict__ out,
                                                   const float* __restrict__ b2, int N) {
    int wid = threadIdx.x >> 5;
    int lane = threadIdx.x & 31;
    int node = blockIdx.x * 8 + wid;
    if (node >= N) return;

    int start = g_rowptr[node];
    int end   = g_rowptr[node + 1];
    int grp = lane / 10;       // 0,1,2 active; lanes 30,31 idle
    int ch  = lane - grp * 10;

    const float4* h = (const float4*)g_h3;
    float4 acc = make_float4(0.f, 0.f, 0.f, 0.f);

    if (grp < 3) {
        for (int k = start + grp; k < end; k += 3) {
            int r = g_perm[k];
            float4 v = __ldg(&h[(size_t)r * 10 + ch]);
            acc.x += v.x; acc.y += v.y; acc.z += v.z; acc.w += v.w;
        }
    }
    acc.x += __shfl_down_sync(0xffffffffu, acc.x, 10) + __shfl_down_sync(0xffffffffu, acc.x, 20);
    acc.y += __shfl_down_sync(0xffffffffu, acc.y, 10) + __shfl_down_sync(0xffffffffu, acc.y, 20);
    acc.z += __shfl_down_sync(0xffffffffu, acc.z, 10) + __shfl_down_sync(0xffffffffu, acc.z, 20);
    acc.w += __shfl_down_sync(0xffffffffu, acc.w, 10) + __shfl_down_sync(0xffffffffu, acc.w, 20);

    if (lane < 10) {
        float di = g_dis[node];
        float4 bb = __ldg(&((const float4*)b2)[ch]);
        acc.x = fmaf(acc.x, di, bb.x);
        acc.y = fmaf(acc.y, di, bb.y);
        acc.z = fmaf(acc.z, di, bb.z);
        acc.w = fmaf(acc.w, di, bb.w);
        ((float4*)out)[(size_t)node * 10 + ch] = acc;
    }
}

// ---------------- launch ----------------
extern "C" void kernel_launch(void* const* d_in, const int* in_sizes, int n_in,
                              void* d_out, int out_size) {
    const float* x = nullptr; const void* ei = nullptr;
    const float* W1 = nullptr; const float* b1 = nullptr;
    const float* W2 = nullptr; const float* b2 = nullptr;
    int x_sz = 0, ei_sz = 0;

    for (int i = 0; i < n_in; i++) {
        int s = in_sizes[i];
        if (s == 8192)       W1 = (const float*)d_in[i];
        else if (s == 2560)  W2 = (const float*)d_in[i];
        else if (s == 64)    b1 = (const float*)d_in[i];
        else if (s == 40)    b2 = (const float*)d_in[i];
        else if (s == 12800000) { x = (const float*)d_in[i]; x_sz = s; }
        else if (s == 3200000)  { ei = d_in[i]; ei_sz = s; }
    }
    if (!x || !ei || !W1 || !b1 || !W2 || !b2) {
        x  = (const float*)d_in[0];  x_sz  = in_sizes[0];
        ei = d_in[1];                ei_sz = in_sizes[1];
        W1 = (const float*)d_in[2];
        b1 = (const float*)d_in[3];
        W2 = (const float*)d_in[4];
        b2 = (const float*)d_in[5];
    }

    float* out = (float*)d_out;
    int N = x_sz / F_IN;
    int E = ei_sz / 2;
    if (N > MAXN) N = MAXN;
    if (E > MAXE) E = MAXE;
    int nb = (N + SCAN_B - 1) / SCAN_B;

    k_zero_detect<<<(N + 255) / 256, 256>>>(ei, N);
    k_count      <<<(E + 255) / 256, 256>>>(ei, E, N);
    k_scan1      <<<nb, SCAN_B>>>(N);
    k_scan23     <<<(N + 255) / 256, 256>>>(N, nb);
    k_fill       <<<(E + 255) / 256, 256>>>(ei, E, N);

    gemm1_kernel<<<(N + 127) / 128, 256>>>(x, W1, N);
    agg1_kernel <<<(N + 7) / 8, 256>>>(N);
    gemm2_kernel<<<(N + 127) / 128, 256>>>(W2, b1, N);
    agg2_kernel <<<(N + 7) / 8, 256>>>(out, b2, N);
}